// round 3
// baseline (speedup 1.0000x reference)
#include <cuda_runtime.h>
#include <cstdint>
#include <float.h>

#define B_ 128
#define H_ 14
#define W_ 14
#define C_ 512
#define C4_ (C_ / 4)
#define HW_ (H_ * W_)
#define ITERS_ 10
#define NCHUNK 4
#define CHUNKLEN 49   // 196 / 4

// Scratch (device globals: no allocs allowed)
__device__ float4 g_pbest4[B_ * NCHUNK * C4_];        // 1 MB partial maxes
__device__ unsigned int g_pidx4[B_ * NCHUNK * C4_];   // 256 KB packed argmax bytes
__device__ unsigned int g_assign_words[(B_ * C_) / 4];

// ---------------------------------------------------------------------------
// Kernel A: partial spatial argmax, float4-wide.
// grid (B, NCHUNK), 128 threads. Thread = one channel-quad; scans CHUNKLEN
// positions with LDG.128 (warp covers 512 contiguous bytes per step).
// ---------------------------------------------------------------------------
__global__ __launch_bounds__(C4_) void argmax_partial_kernel(
    const float4* __restrict__ in4)
{
    const int b = blockIdx.x;
    const int chunk = blockIdx.y;
    const int q = threadIdx.x;

    const float4* base = in4 + ((size_t)b * HW_ + chunk * CHUNKLEN) * C4_ + q;
    float bx = -FLT_MAX, by = -FLT_MAX, bz = -FLT_MAX, bw = -FLT_MAX;
    int ix = 0, iy = 0, iz = 0, iw = 0;
#pragma unroll 7
    for (int i = 0; i < CHUNKLEN; i++) {
        const float4 v = __ldg(base + (size_t)i * C4_);
        if (v.x > bx) { bx = v.x; ix = i; }
        if (v.y > by) { by = v.y; iy = i; }
        if (v.z > bz) { bz = v.z; iz = i; }
        if (v.w > bw) { bw = v.w; iw = i; }
    }
    const int o = (b * NCHUNK + chunk) * C4_ + q;
    g_pbest4[o] = make_float4(bx, by, bz, bw);
    g_pidx4[o] = (unsigned int)ix | ((unsigned int)iy << 8) |
                 ((unsigned int)iz << 16) | ((unsigned int)iw << 24);
}

// ---------------------------------------------------------------------------
// Kernel B: combine partials -> point per channel; 196-bin histogram;
// warp 0 runs the 10 centroid updates with REDUX; all threads classify.
// grid = B, 512 threads. (Partial layout is byte-identical to scalar form.)
// ---------------------------------------------------------------------------
__global__ __launch_bounds__(C_, 1) void kmeans_kernel()
{
    const int b = blockIdx.x;
    const int c = threadIdx.x;

    __shared__ int hist[HW_];
    __shared__ float sinit[4];
    __shared__ float scent[4];

    if (c < HW_) hist[c] = 0;

    const float* pbest = (const float*)g_pbest4;
    const unsigned char* pidx = (const unsigned char*)g_pidx4;

    float best = -FLT_MAX;
    int bestIdx = 0;
#pragma unroll
    for (int k = 0; k < NCHUNK; k++) {
        const int o = (b * NCHUNK + k) * C_ + c;
        const float v = pbest[o];
        if (v > best) { best = v; bestIdx = k * CHUNKLEN + (int)pidx[o]; }
    }
    const float px = (float)(bestIdx % W_);
    const float py = (float)(bestIdx / W_);

    if (c == 0) { sinit[0] = px; sinit[1] = py; }
    if (c == 1) { sinit[2] = px; sinit[3] = py; }
    __syncthreads();

    atomicAdd(&hist[bestIdx], 1);
    __syncthreads();

    if (c < 32) {
        int cnt[7]; float bx[7], by[7];
        int sx = 0, sy = 0;
#pragma unroll
        for (int j = 0; j < 7; j++) {
            const int bin = c * 7 + j;
            const int n = (bin < HW_) ? hist[bin] : 0;
            cnt[j] = n;
            bx[j] = (float)(bin % W_);
            by[j] = (float)(bin / W_);
            sx += n * (bin % W_);
            sy += n * (bin / W_);
        }
        const int Sx = __reduce_add_sync(0xffffffffu, sx);
        const int Sy = __reduce_add_sync(0xffffffffu, sy);

        float c0x = sinit[0], c0y = sinit[1];
        float c1x = sinit[2], c1y = sinit[3];

        for (int it = 0; it < ITERS_; it++) {
            int s1x = 0, s1y = 0, n1 = 0;
#pragma unroll
            for (int j = 0; j < 7; j++) {
                const float dx0 = bx[j] - c0x, dy0 = by[j] - c0y;
                const float dx1 = bx[j] - c1x, dy1 = by[j] - c1y;
                const float d0 = dx0 * dx0 + dy0 * dy0;
                const float d1 = dx1 * dx1 + dy1 * dy1;
                const int m = (d1 < d0) ? cnt[j] : 0;
                n1 += m;
                s1x += m * (int)bx[j];
                s1y += m * (int)by[j];
            }
            const int T1x = __reduce_add_sync(0xffffffffu, s1x);
            const int T1y = __reduce_add_sync(0xffffffffu, s1y);
            const int T1n = __reduce_add_sync(0xffffffffu, n1);

            const float f1n = (float)T1n;
            const float f0n = (float)(C_ - T1n);
            const float inv1 = 1.0f / fmaxf(f1n, 1.0f);
            const float inv0 = 1.0f / fmaxf(f0n, 1.0f);
            c0x = (float)T1x * inv1; c0y = (float)T1y * inv1;
            c1x = (float)(Sx - T1x) * inv0; c1y = (float)(Sy - T1y) * inv0;
        }
        if (c == 0) { scent[0] = c0x; scent[1] = c0y; scent[2] = c1x; scent[3] = c1y; }
    }
    __syncthreads();

    const float dx0 = px - scent[0], dy0 = py - scent[1];
    const float dx1 = px - scent[2], dy1 = py - scent[3];
    const int assign = ((dx1 * dx1 + dy1 * dy1) < (dx0 * dx0 + dy0 * dy0)) ? 1 : 0;
    ((unsigned char*)g_assign_words)[b * C_ + c] = (unsigned char)assign;
}

// ---------------------------------------------------------------------------
// Kernel C: streaming mask split, 2 float4 per thread (split-stride halves,
// both unit-stride coalesced). __stcs so outputs don't evict input from L2.
// ---------------------------------------------------------------------------
#define N4_ ((B_ * HW_ * C_) / 4)
#define HALF4_ (N4_ / 2)

__global__ __launch_bounds__(256) void mask_kernel(
    const float4* __restrict__ in, float4* __restrict__ out0,
    float4* __restrict__ out1)
{
    const int t = blockIdx.x * blockDim.x + threadIdx.x;
    if (t >= HALF4_) return;

#pragma unroll
    for (int h = 0; h < 2; h++) {
        const int i = t + h * HALF4_;
        const int c4 = i & (C4_ - 1);
        const int b = i / (C4_ * HW_);

        const unsigned int am = g_assign_words[b * C4_ + c4];
        const float4 x = __ldg(in + i);

        float4 z0, z1;
        const bool m0 = (am & 0x000000ffu) != 0;
        const bool m1 = (am & 0x0000ff00u) != 0;
        const bool m2 = (am & 0x00ff0000u) != 0;
        const bool m3 = (am & 0xff000000u) != 0;
        z1.x = m0 ? x.x : 0.f;  z0.x = m0 ? 0.f : x.x;
        z1.y = m1 ? x.y : 0.f;  z0.y = m1 ? 0.f : x.y;
        z1.z = m2 ? x.z : 0.f;  z0.z = m2 ? 0.f : x.z;
        z1.w = m3 ? x.w : 0.f;  z0.w = m3 ? 0.f : x.w;

        __stcs(out0 + i, z0);
        __stcs(out1 + i, z1);
    }
}

extern "C" void kernel_launch(void* const* d_in, const int* in_sizes, int n_in,
                              void* d_out, int out_size)
{
    const float* in = (const float*)d_in[0];
    float* out = (float*)d_out;
    const int n_elem = B_ * HW_ * C_;  // 12,845,056

    argmax_partial_kernel<<<dim3(B_, NCHUNK), C4_>>>((const float4*)in);
    kmeans_kernel<<<B_, C_>>>();

    mask_kernel<<<(HALF4_ + 255) / 256, 256>>>((const float4*)in, (float4*)out,
                                               (float4*)(out + n_elem));
}

// round 4
// speedup vs baseline: 1.1161x; 1.1161x over previous
#include <cuda_runtime.h>
#include <cstdint>
#include <float.h>

#define B_ 128
#define H_ 14
#define W_ 14
#define C_ 512
#define C4_ (C_ / 4)
#define HW_ (H_ * W_)
#define ITERS_ 10
#define NCHUNK 14
#define CHUNKLEN 14   // 196 / 14

// Scratch (device globals: no allocs allowed)
__device__ float4 g_pbest4[B_ * NCHUNK * C4_];        // 3.5 MB partial maxes
__device__ unsigned int g_pidx4[B_ * NCHUNK * C4_];   // 0.9 MB packed argmax bytes
__device__ unsigned int g_assign_words[(B_ * C_) / 4];

// ---------------------------------------------------------------------------
// Kernel A: partial spatial argmax, float4-wide, high occupancy.
// grid (B, NCHUNK) = 1792 blocks x 128 threads. Thread = one channel-quad,
// scans CHUNKLEN=14 positions with independent LDG.128s.
// ---------------------------------------------------------------------------
__global__ __launch_bounds__(C4_) void argmax_partial_kernel(
    const float4* __restrict__ in4)
{
    const int b = blockIdx.x;
    const int chunk = blockIdx.y;
    const int q = threadIdx.x;

    const float4* base = in4 + ((size_t)b * HW_ + chunk * CHUNKLEN) * C4_ + q;
    float bx = -FLT_MAX, by = -FLT_MAX, bz = -FLT_MAX, bw = -FLT_MAX;
    int ix = 0, iy = 0, iz = 0, iw = 0;
#pragma unroll
    for (int i = 0; i < CHUNKLEN; i++) {
        const float4 v = __ldg(base + (size_t)i * C4_);
        if (v.x > bx) { bx = v.x; ix = i; }
        if (v.y > by) { by = v.y; iy = i; }
        if (v.z > bz) { bz = v.z; iz = i; }
        if (v.w > bw) { bw = v.w; iw = i; }
    }
    const int o = (b * NCHUNK + chunk) * C4_ + q;
    g_pbest4[o] = make_float4(bx, by, bz, bw);
    g_pidx4[o] = (unsigned int)ix | ((unsigned int)iy << 8) |
                 ((unsigned int)iz << 16) | ((unsigned int)iw << 24);
}

// ---------------------------------------------------------------------------
// Kernel B: combine partials -> point per channel; 196-bin histogram;
// warp 0 runs the 10 centroid updates with REDUX; all threads classify.
// grid = B, 512 threads.
// ---------------------------------------------------------------------------
__global__ __launch_bounds__(C_, 1) void kmeans_kernel()
{
    const int b = blockIdx.x;
    const int c = threadIdx.x;

    __shared__ int hist[HW_];
    __shared__ float sinit[4];
    __shared__ float scent[4];

    if (c < HW_) hist[c] = 0;

    const float* pbest = (const float*)g_pbest4;
    const unsigned char* pidx = (const unsigned char*)g_pidx4;

    // ascending chunk scan with strict '>' keeps first occurrence
    float best = -FLT_MAX;
    int bestIdx = 0;
#pragma unroll
    for (int k = 0; k < NCHUNK; k++) {
        const int o = (b * NCHUNK + k) * C_ + c;
        const float v = pbest[o];
        if (v > best) { best = v; bestIdx = k * CHUNKLEN + (int)pidx[o]; }
    }
    const float px = (float)(bestIdx % W_);
    const float py = (float)(bestIdx / W_);

    if (c == 0) { sinit[0] = px; sinit[1] = py; }
    if (c == 1) { sinit[2] = px; sinit[3] = py; }
    __syncthreads();

    atomicAdd(&hist[bestIdx], 1);
    __syncthreads();

    if (c < 32) {
        int cnt[7]; float bx[7], by[7];
        int sx = 0, sy = 0;
#pragma unroll
        for (int j = 0; j < 7; j++) {
            const int bin = c * 7 + j;
            const int n = (bin < HW_) ? hist[bin] : 0;
            cnt[j] = n;
            bx[j] = (float)(bin % W_);
            by[j] = (float)(bin / W_);
            sx += n * (bin % W_);
            sy += n * (bin / W_);
        }
        const int Sx = __reduce_add_sync(0xffffffffu, sx);
        const int Sy = __reduce_add_sync(0xffffffffu, sy);

        float c0x = sinit[0], c0y = sinit[1];
        float c1x = sinit[2], c1y = sinit[3];

        for (int it = 0; it < ITERS_; it++) {
            int s1x = 0, s1y = 0, n1 = 0;
#pragma unroll
            for (int j = 0; j < 7; j++) {
                const float dx0 = bx[j] - c0x, dy0 = by[j] - c0y;
                const float dx1 = bx[j] - c1x, dy1 = by[j] - c1y;
                const float d0 = dx0 * dx0 + dy0 * dy0;
                const float d1 = dx1 * dx1 + dy1 * dy1;
                const int m = (d1 < d0) ? cnt[j] : 0;
                n1 += m;
                s1x += m * (int)bx[j];
                s1y += m * (int)by[j];
            }
            const int T1x = __reduce_add_sync(0xffffffffu, s1x);
            const int T1y = __reduce_add_sync(0xffffffffu, s1y);
            const int T1n = __reduce_add_sync(0xffffffffu, n1);

            const float inv1 = 1.0f / fmaxf((float)T1n, 1.0f);
            const float inv0 = 1.0f / fmaxf((float)(C_ - T1n), 1.0f);
            // reference swaps clusters each update
            c0x = (float)T1x * inv1; c0y = (float)T1y * inv1;
            c1x = (float)(Sx - T1x) * inv0; c1y = (float)(Sy - T1y) * inv0;
        }
        if (c == 0) { scent[0] = c0x; scent[1] = c0y; scent[2] = c1x; scent[3] = c1y; }
    }
    __syncthreads();

    const float dx0 = px - scent[0], dy0 = py - scent[1];
    const float dx1 = px - scent[2], dy1 = py - scent[3];
    const int assign = ((dx1 * dx1 + dy1 * dy1) < (dx0 * dx0 + dy0 * dy0)) ? 1 : 0;
    ((unsigned char*)g_assign_words)[b * C_ + c] = (unsigned char)assign;
}

// ---------------------------------------------------------------------------
// Kernel C: streaming mask split (round-2 form). float4 per thread; __stcs
// keeps outputs from evicting the (L2-warm) input.
// ---------------------------------------------------------------------------
__global__ __launch_bounds__(256) void mask_kernel(
    const float4* __restrict__ in, float4* __restrict__ out0,
    float4* __restrict__ out1)
{
    const int n4 = (B_ * HW_ * C_) / 4;
    const int i = blockIdx.x * blockDim.x + threadIdx.x;
    if (i >= n4) return;

    const int c4 = i & (C4_ - 1);
    const int b = i / (C4_ * HW_);

    const unsigned int am = g_assign_words[b * C4_ + c4];
    const float4 x = __ldg(in + i);

    float4 z0, z1;
    const bool m0 = (am & 0x000000ffu) != 0;
    const bool m1 = (am & 0x0000ff00u) != 0;
    const bool m2 = (am & 0x00ff0000u) != 0;
    const bool m3 = (am & 0xff000000u) != 0;
    z1.x = m0 ? x.x : 0.f;  z0.x = m0 ? 0.f : x.x;
    z1.y = m1 ? x.y : 0.f;  z0.y = m1 ? 0.f : x.y;
    z1.z = m2 ? x.z : 0.f;  z0.z = m2 ? 0.f : x.z;
    z1.w = m3 ? x.w : 0.f;  z0.w = m3 ? 0.f : x.w;

    __stcs(out0 + i, z0);
    __stcs(out1 + i, z1);
}

extern "C" void kernel_launch(void* const* d_in, const int* in_sizes, int n_in,
                              void* d_out, int out_size)
{
    const float* in = (const float*)d_in[0];
    float* out = (float*)d_out;
    const int n_elem = B_ * HW_ * C_;  // 12,845,056

    argmax_partial_kernel<<<dim3(B_, NCHUNK), C4_>>>((const float4*)in);
    kmeans_kernel<<<B_, C_>>>();

    const int n4 = n_elem / 4;
    mask_kernel<<<(n4 + 255) / 256, 256>>>((const float4*)in, (float4*)out,
                                           (float4*)(out + n_elem));
}